// round 8
// baseline (speedup 1.0000x reference)
#include <cuda_runtime.h>
#include <cuda_bf16.h>

#define TOKENS 2048
#define DDIM   1024
#define PDIM   32
#define NPAT   256
#define TOPK   4
#define NPAIRS (TOKENS * TOPK)            // 8192
#define CHUNK  32
#define MAXCHUNKS (NPAIRS / CHUNK + NPAT) // 512
#define ASPLIT 8
#define WPAD   36

// ---------------- global scratch (static, allocation-free) ----------------
__device__ int   g_eidx[NPAIRS];
__device__ float g_wt[NPAIRS];
__device__ int   g_list[NPAIRS];
__device__ int   g_tiles[MAXCHUNKS];
__device__ int   g_nchunks;
__device__ float g_hwT[DDIM * PDIM];
__device__ float g_keysT[PDIM * NPAT];
__device__ float g_papart[(size_t)NPAIRS * ASPLIT * PDIM];  // 8 MB
__device__ float g_proj[(size_t)NPAIRS * PDIM];             // 1 MB
__device__ uint2 g_poutb[(size_t)NPAIRS * DDIM / 4];        // bf16 pout, 16.8 MB

__device__ __forceinline__ float my_silu(float z) {
    return z / (1.0f + __expf(-z));
}

// ---------------- kernel 0: transpose hasher_w and keys ----------------
__global__ void prep_kernel(const float* __restrict__ hw,
                            const float* __restrict__ keys)
{
    const int tid = blockIdx.x * 256 + threadIdx.x;
    if (tid < (PDIM * DDIM) / 4) {
        const int p  = tid >> 8;
        const float4 v = ((const float4*)hw)[tid];
        const int d = (tid & 255) * 4;
        g_hwT[(d + 0) * PDIM + p] = v.x;
        g_hwT[(d + 1) * PDIM + p] = v.y;
        g_hwT[(d + 2) * PDIM + p] = v.z;
        g_hwT[(d + 3) * PDIM + p] = v.w;
    }
    if (tid < (NPAT * PDIM) / 4) {
        const int n = tid >> 3;
        const int q = tid & 7;
        const float4 v = ((const float4*)keys)[tid];
        g_keysT[(q * 4 + 0) * NPAT + n] = v.x;
        g_keysT[(q * 4 + 1) * NPAT + n] = v.y;
        g_keysT[(q * 4 + 2) * NPAT + n] = v.z;
        g_keysT[(q * 4 + 3) * NPAT + n] = v.w;
    }
}

// ---------------- kernel 1: routing — 8 tokens/block, 256 blocks ----------------
__global__ __launch_bounds__(256)
void routing_kernel(const float* __restrict__ x,
                    const float* __restrict__ scale)
{
    __shared__ float wS[256 * WPAD];   // 36 KB (hw slices, then keysT)
    __shared__ float shh[8][PDIM];

    const int tb   = blockIdx.x * 8;
    const int tid  = threadIdx.x;
    const int warp = tid >> 5;         // token = tb + warp
    const int lane = tid & 31;
    const int tok  = tb + warp;

    const int p4 = lane & 7;
    const int dq = lane >> 3;

    float4 acc = make_float4(0.f, 0.f, 0.f, 0.f);

    for (int slice = 0; slice < 4; slice++) {
        __syncthreads();
        // stage padded hwT slice (256 d x 32 p -> rows of 36)
        {
            const float4* src = (const float4*)(g_hwT + slice * 256 * PDIM);
            #pragma unroll
            for (int k = 0; k < 8; k++) {
                const int i = tid + k * 256;
                const int r = i >> 3, q = i & 7;
                *(float4*)&wS[r * WPAD + q * 4] = src[i];
            }
        }
        __syncthreads();

        const float* xr = x + (size_t)tok * DDIM + slice * 256;
        #pragma unroll 2
        for (int db = 0; db < 256; db += 16) {
            const float4 xv = *(const float4*)(xr + db + dq * 4);   // LDG, 8-way bcast
            const float* wr = wS + (size_t)(db + dq * 4) * WPAD + p4 * 4;
            #pragma unroll
            for (int j = 0; j < 4; j++) {
                const float4 w = *(const float4*)(wr + (size_t)j * WPAD);
                const float s = (j==0)?xv.x:(j==1)?xv.y:(j==2)?xv.z:xv.w;
                acc.x += s*w.x; acc.y += s*w.y; acc.z += s*w.z; acc.w += s*w.w;
            }
        }
    }

    #pragma unroll
    for (int o = 8; o <= 16; o <<= 1) {
        acc.x += __shfl_xor_sync(0xFFFFFFFFu, acc.x, o);
        acc.y += __shfl_xor_sync(0xFFFFFFFFu, acc.y, o);
        acc.z += __shfl_xor_sync(0xFFFFFFFFu, acc.z, o);
        acc.w += __shfl_xor_sync(0xFFFFFFFFu, acc.w, o);
    }
    if (dq == 0) *(float4*)&shh[warp][p4 * 4] = acc;
    __syncthreads();

    // stage keysT (overwrite wS): 8192 floats
    {
        const float4* src = (const float4*)g_keysT;
        #pragma unroll
        for (int k = 0; k < 8; k++)
            ((float4*)wS)[tid + k * 256] = src[tid + k * 256];
    }
    __syncthreads();

    // sims + top-4 per warp (warp = one token)
    float v[8];
    #pragma unroll
    for (int j = 0; j < 8; j++) v[j] = 0.f;
    #pragma unroll 4
    for (int p = 0; p < PDIM; p++) {
        const float hp = shh[warp][p];
        const float* kr = wS + p * NPAT + lane;
        #pragma unroll
        for (int j = 0; j < 8; j++)
            v[j] += hp * kr[32 * j];
    }

    float wv[TOPK]; int widx[TOPK];
    #pragma unroll
    for (int k = 0; k < TOPK; k++) {
        float bv = v[0]; int bj = 0;
        #pragma unroll
        for (int j = 1; j < 8; j++)
            if (v[j] > bv) { bv = v[j]; bj = j; }   // strict >: lower idx wins
        int bidx = lane + 32 * bj;
        #pragma unroll
        for (int o = 16; o; o >>= 1) {
            float ov = __shfl_xor_sync(0xFFFFFFFFu, bv, o);
            int   oi = __shfl_xor_sync(0xFFFFFFFFu, bidx, o);
            if (ov > bv || (ov == bv && oi < bidx)) { bv = ov; bidx = oi; }
        }
        wv[k] = bv; widx[k] = bidx;
        if ((bidx & 31) == lane) v[bidx >> 5] = -1e30f;
    }

    if (lane == 0) {
        float m = wv[0];
        #pragma unroll
        for (int k = 1; k < TOPK; k++) m = fmaxf(m, wv[k]);
        float e[TOPK], s = 0.0f;
        #pragma unroll
        for (int k = 0; k < TOPK; k++) { e[k] = __expf(wv[k] - m); s += e[k]; }
        const float inv = scale[0] / s;
        #pragma unroll
        for (int k = 0; k < TOPK; k++) {
            const int pair = (tok << 2) | k;
            g_eidx[pair] = widx[k];
            g_wt[pair]   = e[k] * inv;
        }
    }
}

// ---------------- kernel 2: scheduler ----------------
__global__ __launch_bounds__(NPAT, 1)
void build_tiles_kernel()
{
    __shared__ int cnt[NPAT];
    __shared__ int scn[NPAT];
    __shared__ int base[NPAT];
    __shared__ int off[NPAT];

    const int t = threadIdx.x;
    cnt[t] = 0; off[t] = 0;
    __syncthreads();

    for (int i = t; i < NPAIRS; i += NPAT)
        atomicAdd(&cnt[g_eidx[i]], 1);
    __syncthreads();

    scn[t] = cnt[t];
    __syncthreads();
    for (int o = 1; o < NPAT; o <<= 1) {
        int add = (t >= o) ? scn[t - o] : 0;
        __syncthreads();
        scn[t] += add;
        __syncthreads();
    }
    base[t] = scn[t] - cnt[t];
    __syncthreads();

    for (int i = t; i < NPAIRS; i += NPAT) {
        const int e = g_eidx[i];
        const int slot = atomicAdd(&off[e], 1);
        g_list[base[e] + slot] = i;
    }

    const int nch = (cnt[t] + CHUNK - 1) / CHUNK;
    scn[t] = nch;
    __syncthreads();
    for (int o = 1; o < NPAT; o <<= 1) {
        int add = (t >= o) ? scn[t - o] : 0;
        __syncthreads();
        scn[t] += add;
        __syncthreads();
    }
    const int cbase = scn[t] - nch;
    for (int i = 0; i < nch; i++) {
        const int start = base[t] + i * CHUNK;
        const int c     = min(CHUNK, cnt[t] - i * CHUNK);
        g_tiles[cbase + i] = (t << 19) | (start << 6) | c;
    }
    if (t == NPAT - 1) g_nchunks = scn[t];
}

// ---------------- kernel 3: phase A — 128 threads, 8 pairs/warp ----------------
__global__ __launch_bounds__(128)
void phaseA_kernel(const float* __restrict__ x,
                   const float* __restrict__ vd)
{
    __shared__ float wS[128 * WPAD];     // 18 KB
    __shared__ float xS[CHUNK * 128];    // 16 KB
    __shared__ int   spair[CHUNK];

    const int chunkId = blockIdx.x >> 3;
    const int dsplit  = blockIdx.x & 7;
    if (chunkId >= g_nchunks) return;

    const int te    = g_tiles[chunkId];
    const int e     = te >> 19;
    const int start = (te >> 6) & 0x1FFF;
    const int cnt   = te & 0x3F;

    const int tid = threadIdx.x;
    if (tid < CHUNK) spair[tid] = g_list[start + min(tid, cnt - 1)];
    __syncthreads();

    // stage Vd slice [128 d][32 p] padded
    {
        const float4* src = (const float4*)(vd + ((size_t)e * DDIM + dsplit * 128) * PDIM);
        #pragma unroll
        for (int k = 0; k < 8; k++) {
            const int i = tid + k * 128;          // 0..1023
            const int r = i >> 3, q = i & 7;
            *(float4*)&wS[r * WPAD + q * 4] = src[i];
        }
    }
    // stage x slices
    {
        const int nld = cnt << 5;
        for (int i = tid; i < nld; i += 128) {
            const int r = i >> 5, c = i & 31;
            ((float4*)xS)[(r << 5) + c] =
                ((const float4*)(x + (size_t)(spair[r] >> 2) * DDIM + dsplit * 128))[c];
        }
    }
    __syncthreads();

    const int warp = tid >> 5;
    const int lane = tid & 31;
    const int g0   = warp * 8;
    if (g0 >= cnt) return;

    const float* xp[8];
    #pragma unroll
    for (int t = 0; t < 8; t++)
        xp[t] = xS + (min(g0 + t, cnt - 1) << 7);

    const int p4 = lane & 7;
    const int dq = lane >> 3;

    float4 acc[8];
    #pragma unroll
    for (int t = 0; t < 8; t++) acc[t] = make_float4(0.f,0.f,0.f,0.f);

    #pragma unroll 4
    for (int db = 0; db < 128; db += 16) {
        float4 xv[8];
        #pragma unroll
        for (int t = 0; t < 8; t++)
            xv[t] = *(const float4*)(xp[t] + db + dq * 4);
        const float* wr = wS + (size_t)(db + dq * 4) * WPAD + p4 * 4;
        #pragma unroll
        for (int j = 0; j < 4; j++) {
            const float4 w = *(const float4*)(wr + (size_t)j * WPAD);
            #pragma unroll
            for (int t = 0; t < 8; t++) {
                const float s = (j==0)?xv[t].x:(j==1)?xv[t].y:(j==2)?xv[t].z:xv[t].w;
                acc[t].x += s*w.x; acc[t].y += s*w.y;
                acc[t].z += s*w.z; acc[t].w += s*w.w;
            }
        }
    }

    #pragma unroll
    for (int t = 0; t < 8; t++) {
        #pragma unroll
        for (int o = 8; o <= 16; o <<= 1) {
            acc[t].x += __shfl_xor_sync(0xFFFFFFFFu, acc[t].x, o);
            acc[t].y += __shfl_xor_sync(0xFFFFFFFFu, acc[t].y, o);
            acc[t].z += __shfl_xor_sync(0xFFFFFFFFu, acc[t].z, o);
            acc[t].w += __shfl_xor_sync(0xFFFFFFFFu, acc[t].w, o);
        }
    }
    if (dq == 0) {
        #pragma unroll
        for (int t = 0; t < 8; t++) {
            if (g0 + t < cnt) {
                float* dst = g_papart
                    + ((size_t)spair[g0 + t] * ASPLIT + dsplit) * PDIM + p4 * 4;
                *(float4*)dst = acc[t];
            }
        }
    }
}

// ---------------- kernel 4: sum partials + silu + weight ----------------
__global__ __launch_bounds__(256)
void silu_kernel()
{
    const int gid  = blockIdx.x * 256 + threadIdx.x;
    const int pair = gid >> 5;
    const int p    = gid & 31;
    const float* pp = g_papart + (size_t)pair * ASPLIT * PDIM + p;
    float s = 0.f;
    #pragma unroll
    for (int j = 0; j < ASPLIT; j++) s += pp[j * PDIM];
    g_proj[(size_t)pair * PDIM + p] = g_wt[pair] * my_silu(s);
}

// ---------------- kernel 5: phase B — 128 threads, 8 pairs/warp, bf16 out ----------------
__global__ __launch_bounds__(128)
void phaseB_kernel(const float* __restrict__ vu)
{
    __shared__ float vuS[PDIM][128];     // 16 KB
    __shared__ float projS[CHUNK][PDIM]; // 4 KB
    __shared__ int   spair[CHUNK];

    const int chunkId = blockIdx.x >> 3;
    const int dsplit  = blockIdx.x & 7;
    if (chunkId >= g_nchunks) return;

    const int te    = g_tiles[chunkId];
    const int e     = te >> 19;
    const int start = (te >> 6) & 0x1FFF;
    const int cnt   = te & 0x3F;

    const int tid = threadIdx.x;
    if (tid < CHUNK) spair[tid] = g_list[start + min(tid, cnt - 1)];
    __syncthreads();

    // stage Vu slice
    {
        const float4* src = (const float4*)(vu + (size_t)e * PDIM * DDIM + dsplit * 128);
        #pragma unroll
        for (int k = 0; k < 8; k++) {
            const int i = tid + k * 128;          // 0..1023
            const int r = i >> 5, c = i & 31;
            ((float4*)vuS[r])[c] = src[(size_t)r * (DDIM / 4) + c];
        }
    }
    // stage proj rows (float4 each, 2 per thread)
    {
        #pragma unroll
        for (int k = 0; k < 2; k++) {
            const int i = tid + k * 128;          // 0..255
            const int pr = i >> 3, q = i & 7;
            *(float4*)&projS[pr][q * 4] =
                *(const float4*)(g_proj + (size_t)spair[pr] * PDIM + q * 4);
        }
    }
    __syncthreads();

    const int warp = tid >> 5;
    const int lane = tid & 31;
    const int g0   = warp * 8;
    if (g0 >= cnt) return;

    int idx[8];
    #pragma unroll
    for (int t = 0; t < 8; t++) idx[t] = min(g0 + t, CHUNK - 1);

    float4 o[8];
    #pragma unroll
    for (int t = 0; t < 8; t++) o[t] = make_float4(0.f,0.f,0.f,0.f);

    #pragma unroll
    for (int pq = 0; pq < 8; pq++) {
        float4 pj[8];
        #pragma unroll
        for (int t = 0; t < 8; t++)
            pj[t] = *(const float4*)&projS[idx[t]][pq * 4];
        #pragma unroll
        for (int j = 0; j < 4; j++) {
            const float4 w = *(const float4*)&vuS[pq * 4 + j][lane * 4];
            #pragma unroll
            for (int t = 0; t < 8; t++) {
                const float s = (j==0)?pj[t].x:(j==1)?pj[t].y:(j==2)?pj[t].z:pj[t].w;
                o[t].x += s*w.x; o[t].y += s*w.y; o[t].z += s*w.z; o[t].w += s*w.w;
            }
        }
    }

    const int dmem = dsplit * 128 + lane * 4;     // float index, /4 -> uint2 index
    #pragma unroll
    for (int t = 0; t < 8; t++) {
        if (g0 + t < cnt) {
            __nv_bfloat162 lo = __floats2bfloat162_rn(o[t].x, o[t].y);
            __nv_bfloat162 hi = __floats2bfloat162_rn(o[t].z, o[t].w);
            uint2 u;
            u.x = *(unsigned int*)&lo;
            u.y = *(unsigned int*)&hi;
            g_poutb[((size_t)spair[g0 + t] * DDIM + dmem) >> 2] = u;
        }
    }
}

// ---------------- kernel 6: combine ----------------
__global__ __launch_bounds__(256)
void combine_kernel(const float* __restrict__ x, float* __restrict__ out)
{
    const int tok = blockIdx.x;
    const int t   = threadIdx.x;
    float4 o = ((const float4*)(x + (size_t)tok * DDIM))[t];
    #pragma unroll
    for (int k = 0; k < TOPK; k++) {
        const uint2 u = g_poutb[((size_t)((tok << 2) | k) * DDIM) / 4 + t];
        const __nv_bfloat162 lo = *(const __nv_bfloat162*)&u.x;
        const __nv_bfloat162 hi = *(const __nv_bfloat162*)&u.y;
        const float2 flo = __bfloat1622float2(lo);
        const float2 fhi = __bfloat1622float2(hi);
        o.x += flo.x; o.y += flo.y; o.z += fhi.x; o.w += fhi.y;
    }
    ((float4*)(out + (size_t)tok * DDIM))[t] = o;
}

// ---------------- launch ----------------
extern "C" void kernel_launch(void* const* d_in, const int* in_sizes, int n_in,
                              void* d_out, int out_size) {
    const float* x     = (const float*)d_in[0];
    const float* hw    = (const float*)d_in[1];
    const float* keys  = (const float*)d_in[2];
    const float* vd    = (const float*)d_in[3];
    const float* vu    = (const float*)d_in[4];
    const float* scale = (const float*)d_in[5];
    float* out = (float*)d_out;

    prep_kernel<<<32, 256>>>(hw, keys);
    routing_kernel<<<TOKENS / 8, 256>>>(x, scale);
    build_tiles_kernel<<<1, NPAT>>>();
    phaseA_kernel<<<MAXCHUNKS * ASPLIT, 128>>>(x, vd);
    silu_kernel<<<NPAIRS * PDIM / 256, 256>>>();
    phaseB_kernel<<<MAXCHUNKS * 8, 128>>>(vu);
    combine_kernel<<<TOKENS, 256>>>(x, out);
}